// round 3
// baseline (speedup 1.0000x reference)
#include <cuda_runtime.h>
#include <cstdint>
#include <math.h>

// ---------------------------------------------------------------------------
// NeuralODE Tsit5 — persistent-CTA fp32 kernel, round 2.
// Transposed activations [N][TM] + row-pair f32x2 packing:
//   - a-pairs load directly as packed u64 (no movs)
//   - warp spans all 4 row-groups -> every shared load is 1 wavefront
//   - 16 ffma2 per 3 LDS.128 + 4 movs per k
// ---------------------------------------------------------------------------

#define BATCH   4096
#define DIM     64
#define WIDTH   256
#define NTT     101
#define TM      32
#define NCTA    (BATCH / TM)      // 128
#define THREADS 256

#define WTILE      8192                // floats per W tile (32KB)
#define WBUF_SIZE  (2 * WTILE)
#define ACT_SIZE   (WIDTH * TM)        // 8192 floats, transposed [N][TM]
#define ZK_SIZE    (DIM * TM)          // 2048 floats, transposed [DIM][TM]

#define SMEM_FLOATS (ACT_SIZE + WBUF_SIZE + ZK_SIZE + ZK_SIZE + 6*ZK_SIZE)
#define SMEM_BYTES  (SMEM_FLOATS * 4)

// Tsit5 tableau
__constant__ float c_A[6][5] = {
    {0.f, 0.f, 0.f, 0.f, 0.f},
    {0.161f, 0.f, 0.f, 0.f, 0.f},
    {-0.008480655492356989f, 0.335480655492357f, 0.f, 0.f, 0.f},
    {2.8971530571054935f, -6.359448489975075f, 4.3622954328695815f, 0.f, 0.f},
    {5.325864828439257f, -11.748883564062828f, 7.4955393428898365f, -0.09249506636175525f, 0.f},
    {5.86145544294642f, -12.92096931784711f, 8.159367898576159f, -0.071584973281401f, -0.028269050394068383f}
};
__constant__ float c_B[6] = {
    0.09646076681806523f, 0.01f, 0.4798896504144996f,
    1.379008574103742f, -3.290069515436081f, 2.324710524099774f
};

// ---- packed f32x2 helpers ----
__device__ __forceinline__ unsigned long long pk2(float lo, float hi) {
    unsigned long long r;
    asm("mov.b64 %0, {%1, %2};" : "=l"(r) : "f"(lo), "f"(hi));
    return r;
}
__device__ __forceinline__ void upk2(unsigned long long v, float &lo, float &hi) {
    asm("mov.b64 {%0, %1}, %2;" : "=f"(lo), "=f"(hi) : "l"(v));
}
__device__ __forceinline__ void ffma2(unsigned long long &d,
                                      unsigned long long a,
                                      unsigned long long b) {
    asm("fma.rn.f32x2 %0, %1, %2, %0;" : "+l"(d) : "l"(a), "l"(b));
}

// ---- cp.async helpers ----
__device__ __forceinline__ void cpa16(float *smem_dst, const float *gmem_src) {
    unsigned s = (unsigned)__cvta_generic_to_shared(smem_dst);
    asm volatile("cp.async.cg.shared.global [%0], [%1], 16;" :: "r"(s), "l"(gmem_src));
}
__device__ __forceinline__ void cpa_commit() {
    asm volatile("cp.async.commit_group;");
}
template <int N>
__device__ __forceinline__ void cpa_wait() {
    asm volatile("cp.async.wait_group %0;" :: "n"(N));
}

// ---------------------------------------------------------------------------
// Dense layer on transposed activations:
//   O^T[N][TM] = act( W^T[N][K] . A^T[K][TM] + b )
// A (input) and O (output) are SMEM, transposed [n*TM + m].
// In-place (A == O) is safe: all reads complete before the epilogue
// (trailing __syncthreads in the tile loop), and the next layer's reads
// are ordered by its own first __syncthreads.
// ---------------------------------------------------------------------------
template <int K, int N, bool ACT>
__device__ __forceinline__ void layerT(const float *__restrict__ A,
                                       float *__restrict__ O,
                                       const float *__restrict__ Wg,
                                       const float *__restrict__ bg,
                                       float *__restrict__ wbuf) {
    constexpr int KC    = WTILE / N;   // 32 (N=256) or 128 (N=64)
    constexpr int TILES = K / KC;      // L0:2  L1/L2:8  L3:2
    constexpr int NT    = (N >= 256) ? 4 : 1;

    const int tid = threadIdx.x;
    const int rg  = tid & 3;           // warp spans all 4 row-groups
    const int cg  = tid >> 2;          // 0..63
    const int r0  = rg * 8;
    const int c0  = cg * NT;

    unsigned long long acc[4][NT];
#pragma unroll
    for (int c = 0; c < NT; c++) {
        float b = __ldg(bg + c0 + c);
        unsigned long long bb = pk2(b, b);
#pragma unroll
        for (int p = 0; p < 4; p++) acc[p][c] = bb;
    }

    // prefetch W tile 0
    for (int i = tid; i < WTILE / 4; i += THREADS)
        cpa16(wbuf + i * 4, Wg + i * 4);
    cpa_commit();

#pragma unroll
    for (int tile = 0; tile < TILES; ++tile) {
        if (tile + 1 < TILES) {
            const float *src = Wg + (tile + 1) * WTILE;
            float *dst = wbuf + ((tile + 1) & 1) * WTILE;
            for (int i = tid; i < WTILE / 4; i += THREADS)
                cpa16(dst + i * 4, src + i * 4);
            cpa_commit();
            cpa_wait<1>();
        } else {
            cpa_wait<0>();
        }
        __syncthreads();

        const float *Wt = wbuf + (tile & 1) * WTILE;
        const float *At = A + tile * KC * TM + r0;

#pragma unroll 8
        for (int k = 0; k < KC; k++) {
            // a row-pairs: rows (r0..r0+7) of column k, already packed
            ulonglong2 a01 = *reinterpret_cast<const ulonglong2 *>(At + k * TM);
            ulonglong2 a23 = *reinterpret_cast<const ulonglong2 *>(At + k * TM + 4);
            unsigned long long ap0 = a01.x, ap1 = a01.y, ap2 = a23.x, ap3 = a23.y;

            unsigned long long wp[NT];
            if constexpr (NT == 4) {
                float4 w = *reinterpret_cast<const float4 *>(Wt + k * N + c0);
                wp[0] = pk2(w.x, w.x);
                wp[1] = pk2(w.y, w.y);
                wp[2] = pk2(w.z, w.z);
                wp[3] = pk2(w.w, w.w);
            } else {
                float w = Wt[k * N + c0];
                wp[0] = pk2(w, w);
            }
#pragma unroll
            for (int c = 0; c < NT; c++) {
                ffma2(acc[0][c], ap0, wp[c]);
                ffma2(acc[1][c], ap1, wp[c]);
                ffma2(acc[2][c], ap2, wp[c]);
                ffma2(acc[3][c], ap3, wp[c]);
            }
        }
        __syncthreads();
    }

    // epilogue: tanh + store transposed (float2 per row-pair)
#pragma unroll
    for (int p = 0; p < 4; p++) {
#pragma unroll
        for (int c = 0; c < NT; c++) {
            float x0, x1;
            upk2(acc[p][c], x0, x1);
            if (ACT) { x0 = tanhf(x0); x1 = tanhf(x1); }
            float2 v; v.x = x0; v.y = x1;
            *reinterpret_cast<float2 *>(O + (c0 + c) * TM + r0 + 2 * p) = v;
        }
    }
}

// ---------------------------------------------------------------------------
__global__ void __launch_bounds__(THREADS, 1)
node_kernel(const float *__restrict__ ts, const float *__restrict__ y0,
            const float *__restrict__ W0, const float *__restrict__ b0,
            const float *__restrict__ W1, const float *__restrict__ b1,
            const float *__restrict__ W2, const float *__restrict__ b2,
            const float *__restrict__ W3, const float *__restrict__ b3,
            float *__restrict__ out) {
    extern __shared__ float sm[];
    float *act0 = sm;                       // 8192 (transposed [256][32])
    float *wbuf = act0 + ACT_SIZE;          // 16384
    float *zbuf = wbuf + WBUF_SIZE;         // 2048  (transposed [64][32])
    float *ybuf = zbuf + ZK_SIZE;           // 2048  (transposed)
    float *kbuf = ybuf + ZK_SIZE;           // 6 * 2048 (transposed)

    const int tid = threadIdx.x;
    const int cta = blockIdx.x;

    // ingest y0 (row-major) -> ybuf (transposed); emit out[0]
    {
        const float *y0c = y0 + (size_t)cta * TM * DIM;
        float *o0 = out + (size_t)cta * TM * DIM;
        for (int i = tid; i < TM * DIM; i += THREADS) {
            float v = __ldg(y0c + i);
            int m = i >> 6;          // DIM = 64
            int d = i & 63;
            ybuf[d * TM + m] = v;
            o0[i] = v;
        }
    }
    __syncthreads();

    for (int t = 1; t < NTT; ++t) {
        const float h = __ldg(ts + t) - __ldg(ts + t - 1);

        for (int s = 0; s < 6; ++s) {
            const float *zin;
            if (s == 0) {
                zin = ybuf;          // z == y for stage 0
            } else {
                // z = y + h * sum_{j<s} A[s][j] * k_j   (transposed, contiguous)
                float4 *zb = reinterpret_cast<float4 *>(zbuf);
                const float4 *yb = reinterpret_cast<const float4 *>(ybuf);
                for (int i = tid; i < ZK_SIZE / 4; i += THREADS) {
                    float4 v = yb[i];
                    for (int j = 0; j < s; j++) {
                        float c = h * c_A[s][j];
                        float4 kv = reinterpret_cast<const float4 *>(kbuf + j * ZK_SIZE)[i];
                        v.x += c * kv.x; v.y += c * kv.y;
                        v.z += c * kv.z; v.w += c * kv.w;
                    }
                    zb[i] = v;
                }
                zin = zbuf;
            }
            __syncthreads();

            layerT<DIM,   WIDTH, true >(zin,  act0, W0, b0, wbuf);
            layerT<WIDTH, WIDTH, true >(act0, act0, W1, b1, wbuf);   // in-place
            layerT<WIDTH, WIDTH, true >(act0, act0, W2, b2, wbuf);   // in-place
            layerT<WIDTH, DIM,   false>(act0, kbuf + s * ZK_SIZE, W3, b3, wbuf);
            __syncthreads();
        }

        // y += h * sum_j B[j] * k_j   (transposed, contiguous)
        {
            float4 *yb = reinterpret_cast<float4 *>(ybuf);
            for (int i = tid; i < ZK_SIZE / 4; i += THREADS) {
                float4 v = yb[i];
#pragma unroll
                for (int j = 0; j < 6; j++) {
                    float c = h * c_B[j];
                    float4 kv = reinterpret_cast<const float4 *>(kbuf + j * ZK_SIZE)[i];
                    v.x += c * kv.x; v.y += c * kv.y;
                    v.z += c * kv.z; v.w += c * kv.w;
                }
                yb[i] = v;
            }
        }
        __syncthreads();

        // store out[t] (row-major, coalesced float4) from transposed ybuf
        {
            float *outc = out + (size_t)t * (BATCH * DIM) + (size_t)cta * TM * DIM;
            for (int i4 = tid; i4 < TM * DIM / 4; i4 += THREADS) {
                int m  = i4 >> 4;    // 16 float4 per batch row
                int dq = (i4 & 15) * 4;
                float4 v;
                v.x = ybuf[(dq + 0) * TM + m];
                v.y = ybuf[(dq + 1) * TM + m];
                v.z = ybuf[(dq + 2) * TM + m];
                v.w = ybuf[(dq + 3) * TM + m];
                reinterpret_cast<float4 *>(outc)[i4] = v;
            }
        }
        __syncthreads();
    }
}

// ---------------------------------------------------------------------------
extern "C" void kernel_launch(void *const *d_in, const int *in_sizes, int n_in,
                              void *d_out, int out_size) {
    const float *ts = (const float *)d_in[0];
    const float *y0 = (const float *)d_in[1];
    const float *W0 = (const float *)d_in[2];
    const float *b0 = (const float *)d_in[3];
    const float *W1 = (const float *)d_in[4];
    const float *b1 = (const float *)d_in[5];
    const float *W2 = (const float *)d_in[6];
    const float *b2 = (const float *)d_in[7];
    const float *W3 = (const float *)d_in[8];
    const float *b3 = (const float *)d_in[9];
    float *out = (float *)d_out;

    cudaFuncSetAttribute(node_kernel,
                         cudaFuncAttributeMaxDynamicSharedMemorySize, SMEM_BYTES);
    node_kernel<<<NCTA, THREADS, SMEM_BYTES>>>(ts, y0, W0, b0, W1, b1,
                                               W2, b2, W3, b3, out);
}